// round 15
// baseline (speedup 1.0000x reference)
#include <cuda_runtime.h>
#include <cuda_fp16.h>

#define TSEQ 4096
#define DM   768
#define NH   12
#define DKH  64
#define DFF  3072
#define NSPLIT_TILES (NH * 16)

// ---- fp32 scratch ----
__device__ float g_y1  [TSEQ * DM];
__device__ float g_y1b [TSEQ * DM];
__device__ float g_y2  [TSEQ * DM];
__device__ float g_y2b [TSEQ * DM];
__device__ float g_bqkv[3 * DM];

// ---- attention split-KV partials + per-tile semaphores ----
__device__ float    g_po[2 * NSPLIT_TILES * 128 * 64];
__device__ float    g_pm[2 * NSPLIT_TILES * 128];
__device__ float    g_pl[2 * NSPLIT_TILES * 128];
__device__ unsigned g_flag[NSPLIT_TILES];

// ---- fp16 activations ----
__device__ __half g_x16[TSEQ * DM];
__device__ __half g_ab [TSEQ * DM];
__device__ __half g_h16[TSEQ * DM];
__device__ __half g_f1 [TSEQ * DFF];

// ---- fp16 transposed weights [N, K] ----
__device__ __half g_wqkv[3 * DM * DM];
__device__ __half g_wo  [DM * DM];
__device__ __half g_w1  [DM * DFF];
__device__ __half g_w2  [DM * DFF];

// ---- fp16 QKV, head-major [NH][TSEQ][64] ----
__device__ __half g_qs[NH * TSEQ * DKH];
__device__ __half g_ks[NH * TSEQ * DKH];
__device__ __half g_vs[NH * TSEQ * DKH];

// ============================================================
// helpers
// ============================================================
__device__ __forceinline__ unsigned s2u(const void* p) {
    unsigned a;
    asm("{ .reg .u64 t; cvta.to.shared.u64 t, %1; cvt.u32.u64 %0, t; }"
        : "=r"(a) : "l"(p));
    return a;
}
__device__ __forceinline__ float ex2(float x) {
    float r;
    asm("ex2.approx.f32 %0, %1;" : "=f"(r) : "f"(x));
    return r;
}
__device__ __forceinline__ void ldm_x4(unsigned* r, unsigned addr) {
    asm volatile("ldmatrix.sync.aligned.m8n8.x4.shared.b16 {%0,%1,%2,%3}, [%4];"
                 : "=r"(r[0]), "=r"(r[1]), "=r"(r[2]), "=r"(r[3]) : "r"(addr));
}
__device__ __forceinline__ void ldm_x4t(unsigned* r, unsigned addr) {
    asm volatile("ldmatrix.sync.aligned.m8n8.x4.trans.shared.b16 {%0,%1,%2,%3}, [%4];"
                 : "=r"(r[0]), "=r"(r[1]), "=r"(r[2]), "=r"(r[3]) : "r"(addr));
}
__device__ __forceinline__ void mma_f16(float* c, const unsigned* a, const unsigned* b) {
    asm volatile("mma.sync.aligned.m16n8k16.row.col.f32.f16.f16.f32 "
                 "{%0,%1,%2,%3}, {%4,%5,%6,%7}, {%8,%9}, {%0,%1,%2,%3};"
                 : "+f"(c[0]), "+f"(c[1]), "+f"(c[2]), "+f"(c[3])
                 : "r"(a[0]), "r"(a[1]), "r"(a[2]), "r"(a[3]), "r"(b[0]), "r"(b[1]));
}
__device__ __forceinline__ void cpa16(unsigned dst, const void* src) {
    asm volatile("cp.async.cg.shared.global [%0], [%1], 16;" :: "r"(dst), "l"(src));
}
__device__ __forceinline__ void cpa16ca(unsigned dst, const void* src) {
    asm volatile("cp.async.ca.shared.global [%0], [%1], 16;" :: "r"(dst), "l"(src));
}
__device__ __forceinline__ void cpa_commit() {
    asm volatile("cp.async.commit_group;" ::: "memory");
}
template<int N> __device__ __forceinline__ void cpa_wait() {
    asm volatile("cp.async.wait_group %0;" :: "n"(N) : "memory");
}

// ============================================================
// ONE prep kernel (+ semaphore reset)
// ============================================================
__device__ __forceinline__ void wconv_body(
    const float* __restrict__ W, __half* __restrict__ T,
    int K, int N, int n0, int k0, float t[32][33])
{
    const int tx = threadIdx.x & 31, ty = threadIdx.x >> 5;
    #pragma unroll
    for (int i = 0; i < 4; i++)
        t[ty + i * 8][tx] = W[(long)(k0 + ty + i * 8) * N + n0 + tx];
    __syncthreads();
    #pragma unroll
    for (int i = 0; i < 4; i++) {
        int n = n0 + ty + i * 8;
        T[(long)n * K + k0 + tx] = __float2half_rn(t[tx][ty + i * 8]);
    }
}
__global__ __launch_bounds__(256) void prep_all(
    const float* __restrict__ Wq, const float* __restrict__ Wk,
    const float* __restrict__ Wv, const float* __restrict__ Wo,
    const float* __restrict__ W1, const float* __restrict__ W2,
    __half* __restrict__ qkv, __half* __restrict__ wo,
    __half* __restrict__ w1, __half* __restrict__ w2,
    const float* __restrict__ X, __half* __restrict__ H,
    const float* __restrict__ bq, const float* __restrict__ bk,
    const float* __restrict__ bv, float* __restrict__ bdst,
    unsigned* __restrict__ flags)
{
    __shared__ float t[32][33];
    int bid = blockIdx.x;
    if (bid < 2304) {
        int z = bid / 576, r = bid % 576;
        const float* W = (z == 0) ? Wq : (z == 1) ? Wk : (z == 2) ? Wv : Wo;
        __half* T = (z < 3) ? (qkv + (long)z * DM * DM) : wo;
        wconv_body(W, T, DM, DM, (r % 24) * 32, (r / 24) * 32, t);
    } else if (bid < 4608) {
        int r = bid - 2304;
        wconv_body(W1, w1, DM, DFF, (r % 96) * 32, (r / 96) * 32, t);
    } else if (bid < 6912) {
        int r = bid - 4608;
        wconv_body(W2, w2, DFF, DM, (r % 24) * 32, (r / 24) * 32, t);
    } else if (bid < 9984) {
        long idx = ((long)(bid - 6912) * 256 + threadIdx.x) * 4;
        float4 v = *(const float4*)(X + idx);
        *(__half2*)(H + idx)     = __floats2half2_rn(v.x, v.y);
        *(__half2*)(H + idx + 2) = __floats2half2_rn(v.z, v.w);
    } else {
        int i = (bid - 9984) * 256 + threadIdx.x;
        if (i < 3 * DM) {
            float v = (i < DM) ? bq[i] : (i < 2 * DM) ? bk[i - DM] : bv[i - 2 * DM];
            bdst[i] = v;
        }
        if (i < NSPLIT_TILES) flags[i] = 0u;   // reset semaphores each call
    }
}

// ============================================================
// fp16 GEMM: BKC=64, 3-stage pipeline (R13 version)
// ============================================================
#define BKC   64
#define ASTR  72
#define SEG   18432
#define STGB  (2 * SEG)
#define GSMEM (3 * STGB)

template<int MODE, bool RELU, bool HASRES, bool RESH, bool SPLITK>
__global__ __launch_bounds__(256, 2)
void gemm_h1(const __half* __restrict__ A, const __half* __restrict__ B,
             const float* __restrict__ bias, const float* __restrict__ res,
             const __half* __restrict__ resh,
             float* __restrict__ Cf, float* __restrict__ Cf2,
             __half* __restrict__ Ch, int K, int N)
{
    extern __shared__ __align__(128) char smem[];
    const int tid   = threadIdx.x;
    const int wid   = tid >> 5;
    const int lane  = tid & 31;
    const int warpM = wid & 1;
    const int warpN = wid >> 1;
    const int brow  = blockIdx.y * 128;
    const int bcol  = blockIdx.x * 128;
    const int kz    = SPLITK ? (int)blockIdx.z : 0;
    const int Keff  = SPLITK ? (K >> 1) : K;
    const int koff  = kz * Keff;
    const unsigned smu = s2u(smem);

    const char* src[2] = { (const char*)A, (const char*)B };

    float acc[4][4][4];
    #pragma unroll
    for (int mi = 0; mi < 4; mi++)
        #pragma unroll
        for (int ni = 0; ni < 4; ni++)
            #pragma unroll
            for (int r = 0; r < 4; r++) acc[mi][ni][r] = 0.f;

    const int nch = Keff / BKC;

    auto load_stage = [&](int s, int kc) {
        #pragma unroll
        for (int it = 0; it < 8; it++) {
            int idx = tid + it * 256;
            int arr = idx >> 10, rem = idx & 1023;
            int row = rem >> 3, ch = rem & 7;
            int base_row = (arr == 0) ? (brow + row) : (bcol + row);
            cpa16(smu + s * STGB + arr * SEG + row * 144 + ch * 16,
                  src[arr] + ((long)base_row * K + koff + kc) * 2 + ch * 16);
        }
    };

    load_stage(0, 0);
    cpa_commit();
    if (nch > 1) { load_stage(1, BKC); cpa_commit(); }

    int s = 0;
    for (int c = 0; c < nch; ++c) {
        cpa_wait<1>();
        __syncthreads();
        if (c + 2 < nch) {
            int s2 = s + 2; if (s2 >= 3) s2 -= 3;
            load_stage(s2, (c + 2) * BKC);
            cpa_commit();
        }

        const unsigned uA = smu + s * STGB;
        const unsigned uB = uA + SEG;

        #pragma unroll
        for (int kk = 0; kk < 4; kk++) {
            unsigned a[4][4];
            #pragma unroll
            for (int mi = 0; mi < 4; mi++) {
                unsigned rowoff =
                    (unsigned)(((warpM * 64 + mi * 16 + (lane & 15)) * ASTR
                                + (lane >> 4) * 8 + kk * 16) * 2);
                ldm_x4(a[mi], uA + rowoff);
            }
            #pragma unroll
            for (int ni = 0; ni < 4; ni += 2) {
                unsigned boff =
                    (unsigned)(((warpN * 32 + (ni + ((lane >> 4) & 1)) * 8 + (lane & 7)) * ASTR
                                + ((lane >> 3) & 1) * 8 + kk * 16) * 2);
                unsigned b[4];
                ldm_x4(b, uB + boff);
                #pragma unroll
                for (int mi = 0; mi < 4; mi++) {
                    mma_f16(acc[mi][ni + 0], a[mi], b);
                    mma_f16(acc[mi][ni + 1], a[mi], b + 2);
                }
            }
        }
        if (++s >= 3) s -= 3;
    }

    #pragma unroll
    for (int mi = 0; mi < 4; mi++) {
        #pragma unroll
        for (int half = 0; half < 2; half++) {
            const int row = brow + warpM * 64 + mi * 16 + (lane >> 2) + half * 8;
            #pragma unroll
            for (int ni = 0; ni < 4; ni++) {
                const int col = bcol + warpN * 32 + ni * 8 + (lane & 3) * 2;
                float2 o;
                o.x = acc[mi][ni][half * 2 + 0];
                o.y = acc[mi][ni][half * 2 + 1];
                if (SPLITK && kz == 1) {
                    *(float2*)(Cf2 + (long)row * N + col) = o;
                    continue;
                }
                o.x += bias[col + 0];
                o.y += bias[col + 1];
                if (RELU) { o.x = fmaxf(o.x, 0.f); o.y = fmaxf(o.y, 0.f); }
                if (HASRES) {
                    if (RESH) {
                        __half2 r2 = *(const __half2*)(resh + (long)row * N + col);
                        float2 rf = __half22float2(r2);
                        o.x += rf.x; o.y += rf.y;
                    } else {
                        float2 r = *(const float2*)(res + (long)row * N + col);
                        o.x += r.x; o.y += r.y;
                    }
                }
                if (MODE == 0) {
                    *(float2*)(Cf + (long)row * N + col) = o;
                } else if (MODE == 1) {
                    *(__half2*)(Ch + (long)row * N + col) = __floats2half2_rn(o.x, o.y);
                } else {
                    int kind = (col >= 2 * DM) ? 2 : ((col >= DM) ? 1 : 0);
                    int cm   = col - kind * DM;
                    if (kind == 0) { o.x *= 0.180336880f; o.y *= 0.180336880f; }
                    int hh = cm >> 6, dd = cm & 63;
                    long off = ((long)hh * TSEQ + row) * DKH + dd;
                    __half2 v = __floats2half2_rn(o.x, o.y);
                    if (kind == 0)      *(__half2*)(g_qs + off) = v;
                    else if (kind == 1) *(__half2*)(g_ks + off) = v;
                    else                *(__half2*)(g_vs + off) = v;
                }
            }
        }
    }
}

// ============================================================
// Tensor-core flash attention, split-KV with FUSED combine:
// the second piece to finish a tile merges both partials.
// ============================================================
#define SM_Q    (128 * 144)
#define KV_ARR  (64 * 144)
#define KV_STG  (2 * KV_ARR)
#define AT_SMEM (SM_Q + 2 * KV_STG)

__global__ __launch_bounds__(256, 2)
void attn_tc(const __half* __restrict__ Qs, const __half* __restrict__ Ks,
             const __half* __restrict__ Vs, __half* __restrict__ O,
             float* __restrict__ po, float* __restrict__ pm,
             float* __restrict__ pl, unsigned* __restrict__ flags)
{
    extern __shared__ __align__(16) char sm[];
    const unsigned smu = s2u(sm);
    const int tid  = threadIdx.x;
    const int lane = tid & 31;
    const int wq   = tid >> 5;
    const int xi   = blockIdx.x;
    const int h    = blockIdx.y;
    const long hb  = (long)h * TSEQ * DKH;

    int qb, kb0, kb1, piece;
    bool split;
    if (xi < 32) {
        qb = 31 - (xi >> 1); piece = xi & 1; split = true;
        const int half = qb + 1;
        kb0 = piece * half; kb1 = kb0 + half;
    } else {
        qb = 15 - (xi - 32); piece = 0; split = false;
        kb0 = 0; kb1 = 2 * (qb + 1);
    }

    {
        const char* sq = (const char*)(Qs + hb + (long)qb * 128 * DKH);
        #pragma unroll
        for (int it = 0; it < 4; it++) {
            int idx = tid + it * 256;
            int row = idx >> 3, ch = idx & 7;
            cpa16ca(smu + row * 144 + ch * 16, sq + row * 128 + ch * 16);
        }
    }
    const char* kvsrc[2] = { (const char*)(Ks + hb), (const char*)(Vs + hb) };
    {
        const long kboff = (long)kb0 * 64;
        #pragma unroll
        for (int it = 0; it < 4; it++) {
            int idx = tid + it * 256;
            int arr = idx >> 9, rem = idx & 511;
            int row = rem >> 3, ch = rem & 7;
            cpa16ca(smu + SM_Q + arr * KV_ARR + row * 144 + ch * 16,
                    kvsrc[arr] + (kboff + row) * 128 + ch * 16);
        }
    }
    cpa_commit();
    cpa_wait<0>();
    __syncthreads();

    unsigned qf[4][4];
    #pragma unroll
    for (int kt = 0; kt < 4; kt++) {
        unsigned a = smu + (wq * 16 + (lane & 15)) * 144
                   + ((lane >> 4) * 8 + kt * 16) * 2;
        ldm_x4(qf[kt], a);
    }

    float o_[8][4];
    #pragma unroll
    for (int i = 0; i < 8; i++)
        #pragma unroll
        for (int j = 0; j < 4; j++) o_[i][j] = 0.f;
    float m0 = -1e30f, m1 = -1e30f, l0 = 0.f, l1 = 0.f;

    const int diagKb = (qb * 128 + wq * 16) >> 6;
    const int r0g    = qb * 128 + wq * 16 + (lane >> 2);

    for (int kb = kb0; kb < kb1; kb++) {
        const int s = (kb - kb0) & 1;

        if (kb + 1 < kb1) {
            const long kbn = (long)(kb + 1) * 64;
            #pragma unroll
            for (int it = 0; it < 4; it++) {
                int idx = tid + it * 256;
                int arr = idx >> 9, rem = idx & 511;
                int row = rem >> 3, ch = rem & 7;
                cpa16ca(smu + SM_Q + (s ^ 1) * KV_STG + arr * KV_ARR + row * 144 + ch * 16,
                        kvsrc[arr] + (kbn + row) * 128 + ch * 16);
            }
        }
        cpa_commit();

        float sc[8][4];
        #pragma unroll
        for (int i = 0; i < 8; i++)
            #pragma unroll
            for (int j = 0; j < 4; j++) sc[i][j] = 0.f;

        const unsigned kbase = smu + SM_Q + s * KV_STG;
        #pragma unroll
        for (int kt = 0; kt < 4; kt++) {
            #pragma unroll
            for (int nt = 0; nt < 8; nt += 2) {
                unsigned ka = kbase
                    + ((nt + ((lane >> 4) & 1)) * 8 + (lane & 7)) * 144
                    + (((lane >> 3) & 1) * 8 + kt * 16) * 2;
                unsigned b[4];
                ldm_x4(b, ka);
                mma_f16(sc[nt + 0], qf[kt], b);
                mma_f16(sc[nt + 1], qf[kt], b + 2);
            }
        }

        if (kb >= diagKb) {
            #pragma unroll
            for (int nt = 0; nt < 8; nt++) {
                int keyb = kb * 64 + nt * 8 + (lane & 3) * 2;
                #pragma unroll
                for (int c = 0; c < 4; c++) {
                    int key = keyb + (c & 1);
                    int row = r0g + (c >> 1) * 8;
                    if (key > row) sc[nt][c] = -1e30f;
                }
            }
        }

        float pm0 = -1e30f, pm1 = -1e30f;
        #pragma unroll
        for (int nt = 0; nt < 8; nt++) {
            pm0 = fmaxf(pm0, fmaxf(sc[nt][0], sc[nt][1]));
            pm1 = fmaxf(pm1, fmaxf(sc[nt][2], sc[nt][3]));
        }
        pm0 = fmaxf(pm0, __shfl_xor_sync(0xffffffffu, pm0, 1));
        pm0 = fmaxf(pm0, __shfl_xor_sync(0xffffffffu, pm0, 2));
        pm1 = fmaxf(pm1, __shfl_xor_sync(0xffffffffu, pm1, 1));
        pm1 = fmaxf(pm1, __shfl_xor_sync(0xffffffffu, pm1, 2));

        float mn0 = fmaxf(m0, pm0), mn1 = fmaxf(m1, pm1);
        float a0 = ex2(m0 - mn0), a1 = ex2(m1 - mn1);
        m0 = mn0; m1 = mn1;

        float rs0 = 0.f, rs1 = 0.f;
        #pragma unroll
        for (int nt = 0; nt < 8; nt++) {
            sc[nt][0] = ex2(sc[nt][0] - mn0);
            sc[nt][1] = ex2(sc[nt][1] - mn0);
            sc[nt][2] = ex2(sc[nt][2] - mn1);
            sc[nt][3] = ex2(sc[nt][3] - mn1);
            rs0 += sc[nt][0] + sc[nt][1];
            rs1 += sc[nt][2] + sc[nt][3];
        }
        rs0 += __shfl_xor_sync(0xffffffffu, rs0, 1);
        rs0 += __shfl_xor_sync(0xffffffffu, rs0, 2);
        rs1 += __shfl_xor_sync(0xffffffffu, rs1, 1);
        rs1 += __shfl_xor_sync(0xffffffffu, rs1, 2);
        l0 = l0 * a0 + rs0;
        l1 = l1 * a1 + rs1;

        #pragma unroll
        for (int dt = 0; dt < 8; dt++) {
            o_[dt][0] *= a0; o_[dt][1] *= a0;
            o_[dt][2] *= a1; o_[dt][3] *= a1;
        }

        unsigned pf[4][4];
        #pragma unroll
        for (int kt = 0; kt < 4; kt++) {
            #pragma unroll
            for (int half = 0; half < 2; half++) {
                const float* v0 = sc[kt * 2 + half];
                __half2 p01 = __floats2half2_rn(v0[0], v0[1]);
                __half2 p23 = __floats2half2_rn(v0[2], v0[3]);
                pf[kt][half * 2 + 0] = *(unsigned*)&p01;
                pf[kt][half * 2 + 1] = *(unsigned*)&p23;
            }
        }

        const unsigned vbase = kbase + KV_ARR;
        #pragma unroll
        for (int kt = 0; kt < 4; kt++) {
            #pragma unroll
            for (int nt = 0; nt < 8; nt += 2) {
                unsigned va = vbase + (kt * 16 + (lane & 15)) * 144
                            + (nt + ((lane >> 4) & 1)) * 16;
                unsigned b[4];
                ldm_x4t(b, va);
                mma_f16(o_[nt + 0], pf[kt], b);
                mma_f16(o_[nt + 1], pf[kt], b + 2);
            }
        }

        cpa_wait<0>();
        __syncthreads();
    }

    if (!split) {
        const float i0 = 1.f / l0, i1 = 1.f / l1;
        #pragma unroll
        for (int nt = 0; nt < 8; nt++) {
            int col = h * DKH + nt * 8 + (lane & 3) * 2;
            *(__half2*)(O + (long)r0g * DM + col) =
                __floats2half2_rn(o_[nt][0] * i0, o_[nt][1] * i0);
            *(__half2*)(O + (long)(r0g + 8) * DM + col) =
                __floats2half2_rn(o_[nt][2] * i1, o_[nt][3] * i1);
        }
        return;
    }

    // ---- split piece: write partials ----
    const int tile = h * 16 + (qb - 16);
    const int lr   = wq * 16 + (lane >> 2);
    float* pob = po + ((long)(piece * NSPLIT_TILES + tile) * 128) * 64;
    #pragma unroll
    for (int nt = 0; nt < 8; nt++) {
        int col = nt * 8 + (lane & 3) * 2;
        *(float2*)(pob + (long)lr * 64 + col)       = make_float2(o_[nt][0], o_[nt][1]);
        *(float2*)(pob + (long)(lr + 8) * 64 + col) = make_float2(o_[nt][2], o_[nt][3]);
    }
    if ((lane & 3) == 0) {
        long mb = (long)(piece * NSPLIT_TILES + tile) * 128;
        pm[mb + lr]     = m0;  pl[mb + lr]     = l0;
        pm[mb + lr + 8] = m1;  pl[mb + lr + 8] = l1;
    }

    // ---- semaphore: second finisher combines ----
    __threadfence();
    __shared__ unsigned s_old;
    __syncthreads();              // all partial stores issued before the arrive
    if (tid == 0) {
        unsigned old;
        asm volatile("atom.global.acq_rel.gpu.add.u32 %0, [%1], 1;"
                     : "=r"(old) : "l"(flags + tile) : "memory");
        s_old = old;
    }
    __syncthreads();
    if (s_old != 1u) return;      // first finisher exits

    __threadfence();              // acquire side for partials of the other piece
    {
        const int row = tid >> 1;             // 0..127
        const int cg  = (tid & 1) * 32;       // 32-col half
        const long mb0 = (long)tile * 128 + row;
        const long mb1 = (long)(NSPLIT_TILES + tile) * 128 + row;
        float cm0 = pm[mb0], cl0 = pl[mb0];
        float cm1 = pm[mb1], cl1 = pl[mb1];
        float mx = fmaxf(cm0, cm1);
        float w0 = ex2(cm0 - mx), w1 = ex2(cm1 - mx);
        float inv = 1.f / (w0 * cl0 + w1 * cl1);
        w0 *= inv; w1 *= inv;

        const float* a = po + ((long)tile * 128 + row) * 64 + cg;
        const float* b = po + ((long)(NSPLIT_TILES + tile) * 128 + row) * 64 + cg;
        __half* dst = O + (long)(qb * 128 + row) * DM + h * DKH + cg;
        #pragma unroll
        for (int c = 0; c < 32; c += 4) {
            float4 av = *(const float4*)(a + c);
            float4 bv = *(const float4*)(b + c);
            *(__half2*)(dst + c)     = __floats2half2_rn(w0 * av.x + w1 * bv.x,
                                                         w0 * av.y + w1 * bv.y);
            *(__half2*)(dst + c + 2) = __floats2half2_rn(w0 * av.z + w1 * bv.z,
                                                         w0 * av.w + w1 * bv.w);
        }
    }
}

// ============================================================
// LayerNorm: warp-per-row vectorized (R13 version)
// ============================================================
template<bool WF32, bool WF16>
__global__ __launch_bounds__(256) void ln_kernel(
    const float* __restrict__ X, const float* __restrict__ X2,
    const float* __restrict__ g, const float* __restrict__ b,
    float* __restrict__ Y, __half* __restrict__ Yh)
{
    const int lane = threadIdx.x & 31;
    const int r    = blockIdx.x * 8 + (threadIdx.x >> 5);
    const float* x  = X  + (long)r * DM;
    const float* x2 = X2 + (long)r * DM;

    float4 v[6];
    float s = 0.f, ss = 0.f;
    #pragma unroll
    for (int j = 0; j < 6; j++) {
        int c = (lane + 32 * j) * 4;
        v[j] = *(const float4*)(x + c);
        float4 w = *(const float4*)(x2 + c);
        v[j].x += w.x; v[j].y += w.y; v[j].z += w.z; v[j].w += w.w;
        s  += v[j].x + v[j].y + v[j].z + v[j].w;
        ss += v[j].x * v[j].x + v[j].y * v[j].y + v[j].z * v[j].z + v[j].w * v[j].w;
    }
    #pragma unroll
    for (int off = 16; off > 0; off >>= 1) {
        s  += __shfl_xor_sync(0xffffffffu, s,  off);
        ss += __shfl_xor_sync(0xffffffffu, ss, off);
    }
    const float mean = s * (1.f / 768.f);
    const float var  = ss * (1.f / 768.f) - mean * mean;
    const float rstd = rsqrtf(var + 1e-5f);

    #pragma unroll
    for (int j = 0; j < 6; j++) {
        int c = (lane + 32 * j) * 4;
        float4 gv = *(const float4*)(g + c);
        float4 bv = *(const float4*)(b + c);
        float4 y;
        y.x = (v[j].x - mean) * rstd * gv.x + bv.x;
        y.y = (v[j].y - mean) * rstd * gv.y + bv.y;
        y.z = (v[j].z - mean) * rstd * gv.z + bv.z;
        y.w = (v[j].w - mean) * rstd * gv.w + bv.w;
        if (WF32) *(float4*)(Y + (long)r * DM + c) = y;
        if (WF16) {
            __half2 h0 = __floats2half2_rn(y.x, y.y);
            __half2 h1 = __floats2half2_rn(y.z, y.w);
            uint2 u = { *(unsigned*)&h0, *(unsigned*)&h1 };
            *(uint2*)(Yh + (long)r * DM + c) = u;
        }
    }
}

// ============================================================
extern "C" void kernel_launch(void* const* d_in, const int* in_sizes, int n_in,
                              void* d_out, int out_size)
{
    const float* x   = (const float*)d_in[0];
    const float* Wq  = (const float*)d_in[1];
    const float* bq  = (const float*)d_in[2];
    const float* Wk  = (const float*)d_in[3];
    const float* bk  = (const float*)d_in[4];
    const float* Wv  = (const float*)d_in[5];
    const float* bv  = (const float*)d_in[6];
    const float* Wo  = (const float*)d_in[7];
    const float* bo  = (const float*)d_in[8];
    const float* W1  = (const float*)d_in[9];
    const float* b1  = (const float*)d_in[10];
    const float* W2  = (const float*)d_in[11];
    const float* b2  = (const float*)d_in[12];
    const float* g1  = (const float*)d_in[13];
    const float* be1 = (const float*)d_in[14];
    const float* g2  = (const float*)d_in[15];
    const float* be2 = (const float*)d_in[16];
    float* out = (float*)d_out;

    float *y1, *y1b, *y2, *y2b, *bqkv, *po, *pmv, *plv;
    unsigned* flags;
    cudaGetSymbolAddress((void**)&y1,   g_y1);
    cudaGetSymbolAddress((void**)&y1b,  g_y1b);
    cudaGetSymbolAddress((void**)&y2,   g_y2);
    cudaGetSymbolAddress((void**)&y2b,  g_y2b);
    cudaGetSymbolAddress((void**)&bqkv, g_bqkv);
    cudaGetSymbolAddress((void**)&po,   g_po);
    cudaGetSymbolAddress((void**)&pmv,  g_pm);
    cudaGetSymbolAddress((void**)&plv,  g_pl);
    cudaGetSymbolAddress((void**)&flags, g_flag);

    __half *x16, *ab, *h16, *f1;
    cudaGetSymbolAddress((void**)&x16, g_x16);
    cudaGetSymbolAddress((void**)&ab,  g_ab);
    cudaGetSymbolAddress((void**)&h16, g_h16);
    cudaGetSymbolAddress((void**)&f1,  g_f1);

    __half *wqkv, *wo, *w1, *w2;
    cudaGetSymbolAddress((void**)&wqkv, g_wqkv);
    cudaGetSymbolAddress((void**)&wo, g_wo);
    cudaGetSymbolAddress((void**)&w1, g_w1);
    cudaGetSymbolAddress((void**)&w2, g_w2);

    __half *qs, *ks, *vs;
    cudaGetSymbolAddress((void**)&qs, g_qs);
    cudaGetSymbolAddress((void**)&ks, g_ks);
    cudaGetSymbolAddress((void**)&vs, g_vs);

    cudaFuncSetAttribute(gemm_h1<2, false, false, false, false>,
                         cudaFuncAttributeMaxDynamicSharedMemorySize, GSMEM);
    cudaFuncSetAttribute(gemm_h1<0, false, true, false, true>,
                         cudaFuncAttributeMaxDynamicSharedMemorySize, GSMEM);
    cudaFuncSetAttribute(gemm_h1<0, false, true, true, true>,
                         cudaFuncAttributeMaxDynamicSharedMemorySize, GSMEM);
    cudaFuncSetAttribute(gemm_h1<1, true, false, false, false>,
                         cudaFuncAttributeMaxDynamicSharedMemorySize, GSMEM);
    cudaFuncSetAttribute(attn_tc, cudaFuncAttributeMaxDynamicSharedMemorySize, AT_SMEM);

    dim3 blk(256);

    prep_all<<<9993, blk>>>(Wq, Wk, Wv, Wo, W1, W2, wqkv, wo, w1, w2,
                            x, x16, bq, bk, bv, bqkv, flags);

    gemm_h1<2, false, false, false, false><<<dim3(18, 32), blk, GSMEM>>>(
        x16, wqkv, bqkv, nullptr, nullptr, nullptr, nullptr, nullptr, DM, 3 * DM);

    // attention with fused split-KV combine (no separate combine kernel)
    attn_tc<<<dim3(48, NH), blk, AT_SMEM>>>(qs, ks, vs, ab, po, pmv, plv, flags);

    gemm_h1<0, false, true, false, true><<<dim3(6, 32, 2), blk, GSMEM>>>(
        ab, wo, bo, x, nullptr, y1, y1b, nullptr, DM, DM);

    ln_kernel<false, true><<<TSEQ / 8, blk>>>(y1, y1b, g1, be1, nullptr, h16);

    gemm_h1<1, true, false, false, false><<<dim3(24, 32), blk, GSMEM>>>(
        h16, w1, b1, nullptr, nullptr, nullptr, nullptr, f1, DM, DFF);
    gemm_h1<0, false, true, true, true><<<dim3(6, 32, 2), blk, GSMEM>>>(
        f1, w2, b2, nullptr, h16, y2, y2b, nullptr, DFF, DM);

    ln_kernel<true, false><<<TSEQ / 8, blk>>>(y2, y2b, g2, be2, out, nullptr);
}

// round 16
// speedup vs baseline: 1.0254x; 1.0254x over previous
#include <cuda_runtime.h>
#include <cuda_fp16.h>

#define TSEQ 4096
#define DM   768
#define NH   12
#define DKH  64
#define DFF  3072
#define NSPLIT_TILES (NH * 16)

// ---- fp32 scratch ----
__device__ float g_y1  [TSEQ * DM];
__device__ float g_y1b [TSEQ * DM];
__device__ float g_y2  [TSEQ * DM];
__device__ float g_y2b [TSEQ * DM];
__device__ float g_bqkv[3 * DM];

// ---- attention split-KV partials ----
__device__ float g_po[2 * NSPLIT_TILES * 128 * 64];
__device__ float g_pm[2 * NSPLIT_TILES * 128];
__device__ float g_pl[2 * NSPLIT_TILES * 128];

// ---- fp16 activations ----
__device__ __half g_x16[TSEQ * DM];
__device__ __half g_ab [TSEQ * DM];
__device__ __half g_h16[TSEQ * DM];
__device__ __half g_f1 [TSEQ * DFF];

// ---- fp16 transposed weights [N, K] ----
__device__ __half g_wqkv[3 * DM * DM];
__device__ __half g_wo  [DM * DM];
__device__ __half g_w1  [DM * DFF];
__device__ __half g_w2  [DM * DFF];

// ---- fp16 QKV, head-major [NH][TSEQ][64] ----
__device__ __half g_qs[NH * TSEQ * DKH];
__device__ __half g_ks[NH * TSEQ * DKH];
__device__ __half g_vs[NH * TSEQ * DKH];

// ============================================================
// helpers
// ============================================================
__device__ __forceinline__ unsigned s2u(const void* p) {
    unsigned a;
    asm("{ .reg .u64 t; cvta.to.shared.u64 t, %1; cvt.u32.u64 %0, t; }"
        : "=r"(a) : "l"(p));
    return a;
}
__device__ __forceinline__ float ex2(float x) {
    float r;
    asm("ex2.approx.f32 %0, %1;" : "=f"(r) : "f"(x));
    return r;
}
__device__ __forceinline__ void ldm_x4(unsigned* r, unsigned addr) {
    asm volatile("ldmatrix.sync.aligned.m8n8.x4.shared.b16 {%0,%1,%2,%3}, [%4];"
                 : "=r"(r[0]), "=r"(r[1]), "=r"(r[2]), "=r"(r[3]) : "r"(addr));
}
__device__ __forceinline__ void ldm_x4t(unsigned* r, unsigned addr) {
    asm volatile("ldmatrix.sync.aligned.m8n8.x4.trans.shared.b16 {%0,%1,%2,%3}, [%4];"
                 : "=r"(r[0]), "=r"(r[1]), "=r"(r[2]), "=r"(r[3]) : "r"(addr));
}
__device__ __forceinline__ void mma_f16(float* c, const unsigned* a, const unsigned* b) {
    asm volatile("mma.sync.aligned.m16n8k16.row.col.f32.f16.f16.f32 "
                 "{%0,%1,%2,%3}, {%4,%5,%6,%7}, {%8,%9}, {%0,%1,%2,%3};"
                 : "+f"(c[0]), "+f"(c[1]), "+f"(c[2]), "+f"(c[3])
                 : "r"(a[0]), "r"(a[1]), "r"(a[2]), "r"(a[3]), "r"(b[0]), "r"(b[1]));
}
__device__ __forceinline__ void cpa16(unsigned dst, const void* src) {
    asm volatile("cp.async.cg.shared.global [%0], [%1], 16;" :: "r"(dst), "l"(src));
}
__device__ __forceinline__ void cpa16ca(unsigned dst, const void* src) {
    asm volatile("cp.async.ca.shared.global [%0], [%1], 16;" :: "r"(dst), "l"(src));
}
__device__ __forceinline__ void cpa_commit() {
    asm volatile("cp.async.commit_group;" ::: "memory");
}
template<int N> __device__ __forceinline__ void cpa_wait() {
    asm volatile("cp.async.wait_group %0;" :: "n"(N) : "memory");
}

// ============================================================
// ONE prep kernel (R13)
// ============================================================
__device__ __forceinline__ void wconv_body(
    const float* __restrict__ W, __half* __restrict__ T,
    int K, int N, int n0, int k0, float t[32][33])
{
    const int tx = threadIdx.x & 31, ty = threadIdx.x >> 5;
    #pragma unroll
    for (int i = 0; i < 4; i++)
        t[ty + i * 8][tx] = W[(long)(k0 + ty + i * 8) * N + n0 + tx];
    __syncthreads();
    #pragma unroll
    for (int i = 0; i < 4; i++) {
        int n = n0 + ty + i * 8;
        T[(long)n * K + k0 + tx] = __float2half_rn(t[tx][ty + i * 8]);
    }
}
__global__ __launch_bounds__(256) void prep_all(
    const float* __restrict__ Wq, const float* __restrict__ Wk,
    const float* __restrict__ Wv, const float* __restrict__ Wo,
    const float* __restrict__ W1, const float* __restrict__ W2,
    __half* __restrict__ qkv, __half* __restrict__ wo,
    __half* __restrict__ w1, __half* __restrict__ w2,
    const float* __restrict__ X, __half* __restrict__ H,
    const float* __restrict__ bq, const float* __restrict__ bk,
    const float* __restrict__ bv, float* __restrict__ bdst)
{
    __shared__ float t[32][33];
    int bid = blockIdx.x;
    if (bid < 2304) {
        int z = bid / 576, r = bid % 576;
        const float* W = (z == 0) ? Wq : (z == 1) ? Wk : (z == 2) ? Wv : Wo;
        __half* T = (z < 3) ? (qkv + (long)z * DM * DM) : wo;
        wconv_body(W, T, DM, DM, (r % 24) * 32, (r / 24) * 32, t);
    } else if (bid < 4608) {
        int r = bid - 2304;
        wconv_body(W1, w1, DM, DFF, (r % 96) * 32, (r / 96) * 32, t);
    } else if (bid < 6912) {
        int r = bid - 4608;
        wconv_body(W2, w2, DFF, DM, (r % 24) * 32, (r / 24) * 32, t);
    } else if (bid < 9984) {
        long idx = ((long)(bid - 6912) * 256 + threadIdx.x) * 4;
        float4 v = *(const float4*)(X + idx);
        *(__half2*)(H + idx)     = __floats2half2_rn(v.x, v.y);
        *(__half2*)(H + idx + 2) = __floats2half2_rn(v.z, v.w);
    } else {
        int i = (bid - 9984) * 256 + threadIdx.x;
        if (i < 3 * DM) {
            float v = (i < DM) ? bq[i] : (i < 2 * DM) ? bk[i - DM] : bv[i - 2 * DM];
            bdst[i] = v;
        }
    }
}

// ============================================================
// fp16 GEMM: BKC=64, 3-stage pipeline (R13)
// ============================================================
#define BKC   64
#define ASTR  72
#define SEG   18432
#define STGB  (2 * SEG)
#define GSMEM (3 * STGB)

template<int MODE, bool RELU, bool HASRES, bool RESH, bool SPLITK>
__global__ __launch_bounds__(256, 2)
void gemm_h1(const __half* __restrict__ A, const __half* __restrict__ B,
             const float* __restrict__ bias, const float* __restrict__ res,
             const __half* __restrict__ resh,
             float* __restrict__ Cf, float* __restrict__ Cf2,
             __half* __restrict__ Ch, int K, int N)
{
    extern __shared__ __align__(128) char smem[];
    const int tid   = threadIdx.x;
    const int wid   = tid >> 5;
    const int lane  = tid & 31;
    const int warpM = wid & 1;
    const int warpN = wid >> 1;
    const int brow  = blockIdx.y * 128;
    const int bcol  = blockIdx.x * 128;
    const int kz    = SPLITK ? (int)blockIdx.z : 0;
    const int Keff  = SPLITK ? (K >> 1) : K;
    const int koff  = kz * Keff;
    const unsigned smu = s2u(smem);

    const char* src[2] = { (const char*)A, (const char*)B };

    float acc[4][4][4];
    #pragma unroll
    for (int mi = 0; mi < 4; mi++)
        #pragma unroll
        for (int ni = 0; ni < 4; ni++)
            #pragma unroll
            for (int r = 0; r < 4; r++) acc[mi][ni][r] = 0.f;

    const int nch = Keff / BKC;

    auto load_stage = [&](int s, int kc) {
        #pragma unroll
        for (int it = 0; it < 8; it++) {
            int idx = tid + it * 256;
            int arr = idx >> 10, rem = idx & 1023;
            int row = rem >> 3, ch = rem & 7;
            int base_row = (arr == 0) ? (brow + row) : (bcol + row);
            cpa16(smu + s * STGB + arr * SEG + row * 144 + ch * 16,
                  src[arr] + ((long)base_row * K + koff + kc) * 2 + ch * 16);
        }
    };

    load_stage(0, 0);
    cpa_commit();
    if (nch > 1) { load_stage(1, BKC); cpa_commit(); }

    int s = 0;
    for (int c = 0; c < nch; ++c) {
        cpa_wait<1>();
        __syncthreads();
        if (c + 2 < nch) {
            int s2 = s + 2; if (s2 >= 3) s2 -= 3;
            load_stage(s2, (c + 2) * BKC);
            cpa_commit();
        }

        const unsigned uA = smu + s * STGB;
        const unsigned uB = uA + SEG;

        #pragma unroll
        for (int kk = 0; kk < 4; kk++) {
            unsigned a[4][4];
            #pragma unroll
            for (int mi = 0; mi < 4; mi++) {
                unsigned rowoff =
                    (unsigned)(((warpM * 64 + mi * 16 + (lane & 15)) * ASTR
                                + (lane >> 4) * 8 + kk * 16) * 2);
                ldm_x4(a[mi], uA + rowoff);
            }
            #pragma unroll
            for (int ni = 0; ni < 4; ni += 2) {
                unsigned boff =
                    (unsigned)(((warpN * 32 + (ni + ((lane >> 4) & 1)) * 8 + (lane & 7)) * ASTR
                                + ((lane >> 3) & 1) * 8 + kk * 16) * 2);
                unsigned b[4];
                ldm_x4(b, uB + boff);
                #pragma unroll
                for (int mi = 0; mi < 4; mi++) {
                    mma_f16(acc[mi][ni + 0], a[mi], b);
                    mma_f16(acc[mi][ni + 1], a[mi], b + 2);
                }
            }
        }
        if (++s >= 3) s -= 3;
    }

    #pragma unroll
    for (int mi = 0; mi < 4; mi++) {
        #pragma unroll
        for (int half = 0; half < 2; half++) {
            const int row = brow + warpM * 64 + mi * 16 + (lane >> 2) + half * 8;
            #pragma unroll
            for (int ni = 0; ni < 4; ni++) {
                const int col = bcol + warpN * 32 + ni * 8 + (lane & 3) * 2;
                float2 o;
                o.x = acc[mi][ni][half * 2 + 0];
                o.y = acc[mi][ni][half * 2 + 1];
                if (SPLITK && kz == 1) {
                    *(float2*)(Cf2 + (long)row * N + col) = o;
                    continue;
                }
                o.x += bias[col + 0];
                o.y += bias[col + 1];
                if (RELU) { o.x = fmaxf(o.x, 0.f); o.y = fmaxf(o.y, 0.f); }
                if (HASRES) {
                    if (RESH) {
                        __half2 r2 = *(const __half2*)(resh + (long)row * N + col);
                        float2 rf = __half22float2(r2);
                        o.x += rf.x; o.y += rf.y;
                    } else {
                        float2 r = *(const float2*)(res + (long)row * N + col);
                        o.x += r.x; o.y += r.y;
                    }
                }
                if (MODE == 0) {
                    *(float2*)(Cf + (long)row * N + col) = o;
                } else if (MODE == 1) {
                    *(__half2*)(Ch + (long)row * N + col) = __floats2half2_rn(o.x, o.y);
                } else {
                    int kind = (col >= 2 * DM) ? 2 : ((col >= DM) ? 1 : 0);
                    int cm   = col - kind * DM;
                    if (kind == 0) { o.x *= 0.180336880f; o.y *= 0.180336880f; }
                    int hh = cm >> 6, dd = cm & 63;
                    long off = ((long)hh * TSEQ + row) * DKH + dd;
                    __half2 v = __floats2half2_rn(o.x, o.y);
                    if (kind == 0)      *(__half2*)(g_qs + off) = v;
                    else if (kind == 1) *(__half2*)(g_ks + off) = v;
                    else                *(__half2*)(g_vs + off) = v;
                }
            }
        }
    }
}

// ============================================================
// Tensor-core flash attention, split-KV (R13)
// ============================================================
#define SM_Q    (128 * 144)
#define KV_ARR  (64 * 144)
#define KV_STG  (2 * KV_ARR)
#define AT_SMEM (SM_Q + 2 * KV_STG)

__global__ __launch_bounds__(256, 2)
void attn_tc(const __half* __restrict__ Qs, const __half* __restrict__ Ks,
             const __half* __restrict__ Vs, __half* __restrict__ O,
             float* __restrict__ po, float* __restrict__ pm,
             float* __restrict__ pl)
{
    extern __shared__ __align__(16) char sm[];
    const unsigned smu = s2u(sm);
    const int tid  = threadIdx.x;
    const int lane = tid & 31;
    const int wq   = tid >> 5;
    const int xi   = blockIdx.x;
    const int h    = blockIdx.y;
    const long hb  = (long)h * TSEQ * DKH;

    int qb, kb0, kb1, piece;
    bool split;
    if (xi < 32) {
        qb = 31 - (xi >> 1); piece = xi & 1; split = true;
        const int half = qb + 1;
        kb0 = piece * half; kb1 = kb0 + half;
    } else {
        qb = 15 - (xi - 32); piece = 0; split = false;
        kb0 = 0; kb1 = 2 * (qb + 1);
    }

    {
        const char* sq = (const char*)(Qs + hb + (long)qb * 128 * DKH);
        #pragma unroll
        for (int it = 0; it < 4; it++) {
            int idx = tid + it * 256;
            int row = idx >> 3, ch = idx & 7;
            cpa16ca(smu + row * 144 + ch * 16, sq + row * 128 + ch * 16);
        }
    }
    const char* kvsrc[2] = { (const char*)(Ks + hb), (const char*)(Vs + hb) };
    {
        const long kboff = (long)kb0 * 64;
        #pragma unroll
        for (int it = 0; it < 4; it++) {
            int idx = tid + it * 256;
            int arr = idx >> 9, rem = idx & 511;
            int row = rem >> 3, ch = rem & 7;
            cpa16ca(smu + SM_Q + arr * KV_ARR + row * 144 + ch * 16,
                    kvsrc[arr] + (kboff + row) * 128 + ch * 16);
        }
    }
    cpa_commit();
    cpa_wait<0>();
    __syncthreads();

    unsigned qf[4][4];
    #pragma unroll
    for (int kt = 0; kt < 4; kt++) {
        unsigned a = smu + (wq * 16 + (lane & 15)) * 144
                   + ((lane >> 4) * 8 + kt * 16) * 2;
        ldm_x4(qf[kt], a);
    }

    float o_[8][4];
    #pragma unroll
    for (int i = 0; i < 8; i++)
        #pragma unroll
        for (int j = 0; j < 4; j++) o_[i][j] = 0.f;
    float m0 = -1e30f, m1 = -1e30f, l0 = 0.f, l1 = 0.f;

    const int diagKb = (qb * 128 + wq * 16) >> 6;
    const int r0g    = qb * 128 + wq * 16 + (lane >> 2);

    for (int kb = kb0; kb < kb1; kb++) {
        const int s = (kb - kb0) & 1;

        if (kb + 1 < kb1) {
            const long kbn = (long)(kb + 1) * 64;
            #pragma unroll
            for (int it = 0; it < 4; it++) {
                int idx = tid + it * 256;
                int arr = idx >> 9, rem = idx & 511;
                int row = rem >> 3, ch = rem & 7;
                cpa16ca(smu + SM_Q + (s ^ 1) * KV_STG + arr * KV_ARR + row * 144 + ch * 16,
                        kvsrc[arr] + (kbn + row) * 128 + ch * 16);
            }
        }
        cpa_commit();

        float sc[8][4];
        #pragma unroll
        for (int i = 0; i < 8; i++)
            #pragma unroll
            for (int j = 0; j < 4; j++) sc[i][j] = 0.f;

        const unsigned kbase = smu + SM_Q + s * KV_STG;
        #pragma unroll
        for (int kt = 0; kt < 4; kt++) {
            #pragma unroll
            for (int nt = 0; nt < 8; nt += 2) {
                unsigned ka = kbase
                    + ((nt + ((lane >> 4) & 1)) * 8 + (lane & 7)) * 144
                    + (((lane >> 3) & 1) * 8 + kt * 16) * 2;
                unsigned b[4];
                ldm_x4(b, ka);
                mma_f16(sc[nt + 0], qf[kt], b);
                mma_f16(sc[nt + 1], qf[kt], b + 2);
            }
        }

        if (kb >= diagKb) {
            #pragma unroll
            for (int nt = 0; nt < 8; nt++) {
                int keyb = kb * 64 + nt * 8 + (lane & 3) * 2;
                #pragma unroll
                for (int c = 0; c < 4; c++) {
                    int key = keyb + (c & 1);
                    int row = r0g + (c >> 1) * 8;
                    if (key > row) sc[nt][c] = -1e30f;
                }
            }
        }

        float pm0 = -1e30f, pm1 = -1e30f;
        #pragma unroll
        for (int nt = 0; nt < 8; nt++) {
            pm0 = fmaxf(pm0, fmaxf(sc[nt][0], sc[nt][1]));
            pm1 = fmaxf(pm1, fmaxf(sc[nt][2], sc[nt][3]));
        }
        pm0 = fmaxf(pm0, __shfl_xor_sync(0xffffffffu, pm0, 1));
        pm0 = fmaxf(pm0, __shfl_xor_sync(0xffffffffu, pm0, 2));
        pm1 = fmaxf(pm1, __shfl_xor_sync(0xffffffffu, pm1, 1));
        pm1 = fmaxf(pm1, __shfl_xor_sync(0xffffffffu, pm1, 2));

        float mn0 = fmaxf(m0, pm0), mn1 = fmaxf(m1, pm1);
        float a0 = ex2(m0 - mn0), a1 = ex2(m1 - mn1);
        m0 = mn0; m1 = mn1;

        float rs0 = 0.f, rs1 = 0.f;
        #pragma unroll
        for (int nt = 0; nt < 8; nt++) {
            sc[nt][0] = ex2(sc[nt][0] - mn0);
            sc[nt][1] = ex2(sc[nt][1] - mn0);
            sc[nt][2] = ex2(sc[nt][2] - mn1);
            sc[nt][3] = ex2(sc[nt][3] - mn1);
            rs0 += sc[nt][0] + sc[nt][1];
            rs1 += sc[nt][2] + sc[nt][3];
        }
        rs0 += __shfl_xor_sync(0xffffffffu, rs0, 1);
        rs0 += __shfl_xor_sync(0xffffffffu, rs0, 2);
        rs1 += __shfl_xor_sync(0xffffffffu, rs1, 1);
        rs1 += __shfl_xor_sync(0xffffffffu, rs1, 2);
        l0 = l0 * a0 + rs0;
        l1 = l1 * a1 + rs1;

        #pragma unroll
        for (int dt = 0; dt < 8; dt++) {
            o_[dt][0] *= a0; o_[dt][1] *= a0;
            o_[dt][2] *= a1; o_[dt][3] *= a1;
        }

        unsigned pf[4][4];
        #pragma unroll
        for (int kt = 0; kt < 4; kt++) {
            #pragma unroll
            for (int half = 0; half < 2; half++) {
                const float* v0 = sc[kt * 2 + half];
                __half2 p01 = __floats2half2_rn(v0[0], v0[1]);
                __half2 p23 = __floats2half2_rn(v0[2], v0[3]);
                pf[kt][half * 2 + 0] = *(unsigned*)&p01;
                pf[kt][half * 2 + 1] = *(unsigned*)&p23;
            }
        }

        const unsigned vbase = kbase + KV_ARR;
        #pragma unroll
        for (int kt = 0; kt < 4; kt++) {
            #pragma unroll
            for (int nt = 0; nt < 8; nt += 2) {
                unsigned va = vbase + (kt * 16 + (lane & 15)) * 144
                            + (nt + ((lane >> 4) & 1)) * 16;
                unsigned b[4];
                ldm_x4t(b, va);
                mma_f16(o_[nt + 0], pf[kt], b);
                mma_f16(o_[nt + 1], pf[kt], b + 2);
            }
        }

        cpa_wait<0>();
        __syncthreads();
    }

    if (!split) {
        const float i0 = 1.f / l0, i1 = 1.f / l1;
        #pragma unroll
        for (int nt = 0; nt < 8; nt++) {
            int col = h * DKH + nt * 8 + (lane & 3) * 2;
            *(__half2*)(O + (long)r0g * DM + col) =
                __floats2half2_rn(o_[nt][0] * i0, o_[nt][1] * i0);
            *(__half2*)(O + (long)(r0g + 8) * DM + col) =
                __floats2half2_rn(o_[nt][2] * i1, o_[nt][3] * i1);
        }
    } else {
        const int tile = h * 16 + (qb - 16);
        const int lr   = wq * 16 + (lane >> 2);
        float* pob = po + ((long)(piece * NSPLIT_TILES + tile) * 128) * 64;
        #pragma unroll
        for (int nt = 0; nt < 8; nt++) {
            int col = nt * 8 + (lane & 3) * 2;
            *(float2*)(pob + (long)lr * 64 + col)       = make_float2(o_[nt][0], o_[nt][1]);
            *(float2*)(pob + (long)(lr + 8) * 64 + col) = make_float2(o_[nt][2], o_[nt][3]);
        }
        if ((lane & 3) == 0) {
            long mb = (long)(piece * NSPLIT_TILES + tile) * 128;
            pm[mb + lr]     = m0;  pl[mb + lr]     = l0;
            pm[mb + lr + 8] = m1;  pl[mb + lr + 8] = l1;
        }
    }
}

// ============================================================
// Combine split-KV partials: 8 blocks/tile, 4 cols/thread
// (2048 threads per tile — 2x parallelism vs R13)
// ============================================================
__global__ __launch_bounds__(256) void attn_combine(
    const float* __restrict__ po, const float* __restrict__ pm,
    const float* __restrict__ pl, __half* __restrict__ O)
{
    const int tile = blockIdx.x >> 3;
    const int t    = (blockIdx.x & 7) * 256 + threadIdx.x;   // 0..2047
    const int row  = t >> 4;                                 // 0..127
    const int cg   = (t & 15) * 4;                           // col group of 4
    const int h    = tile / 16;
    const int qb   = 16 + (tile % 16);

    const long mb0 = (long)tile * 128 + row;
    const long mb1 = (long)(NSPLIT_TILES + tile) * 128 + row;
    float m0 = pm[mb0], l0 = pl[mb0];
    float m1 = pm[mb1], l1 = pl[mb1];
    float mx = fmaxf(m0, m1);
    float w0 = ex2(m0 - mx), w1 = ex2(m1 - mx);
    float inv = 1.f / (w0 * l0 + w1 * l1);
    w0 *= inv; w1 *= inv;

    const float* a = po + ((long)tile * 128 + row) * 64 + cg;
    const float* b = po + ((long)(NSPLIT_TILES + tile) * 128 + row) * 64 + cg;
    __half* dst = O + (long)(qb * 128 + row) * DM + h * DKH + cg;
    float4 av = *(const float4*)a;
    float4 bv = *(const float4*)b;
    *(__half2*)(dst)     = __floats2half2_rn(w0 * av.x + w1 * bv.x,
                                             w0 * av.y + w1 * bv.y);
    *(__half2*)(dst + 2) = __floats2half2_rn(w0 * av.z + w1 * bv.z,
                                             w0 * av.w + w1 * bv.w);
}

// ============================================================
// LayerNorm: warp-per-row vectorized (R13)
// ============================================================
template<bool WF32, bool WF16>
__global__ __launch_bounds__(256) void ln_kernel(
    const float* __restrict__ X, const float* __restrict__ X2,
    const float* __restrict__ g, const float* __restrict__ b,
    float* __restrict__ Y, __half* __restrict__ Yh)
{
    const int lane = threadIdx.x & 31;
    const int r    = blockIdx.x * 8 + (threadIdx.x >> 5);
    const float* x  = X  + (long)r * DM;
    const float* x2 = X2 + (long)r * DM;

    float4 v[6];
    float s = 0.f, ss = 0.f;
    #pragma unroll
    for (int j = 0; j < 6; j++) {
        int c = (lane + 32 * j) * 4;
        v[j] = *(const float4*)(x + c);
        float4 w = *(const float4*)(x2 + c);
        v[j].x += w.x; v[j].y += w.y; v[j].z += w.z; v[j].w += w.w;
        s  += v[j].x + v[j].y + v[j].z + v[j].w;
        ss += v[j].x * v[j].x + v[j].y * v[j].y + v[j].z * v[j].z + v[j].w * v[j].w;
    }
    #pragma unroll
    for (int off = 16; off > 0; off >>= 1) {
        s  += __shfl_xor_sync(0xffffffffu, s,  off);
        ss += __shfl_xor_sync(0xffffffffu, ss, off);
    }
    const float mean = s * (1.f / 768.f);
    const float var  = ss * (1.f / 768.f) - mean * mean;
    const float rstd = rsqrtf(var + 1e-5f);

    #pragma unroll
    for (int j = 0; j < 6; j++) {
        int c = (lane + 32 * j) * 4;
        float4 gv = *(const float4*)(g + c);
        float4 bv = *(const float4*)(b + c);
        float4 y;
        y.x = (v[j].x - mean) * rstd * gv.x + bv.x;
        y.y = (v[j].y - mean) * rstd * gv.y + bv.y;
        y.z = (v[j].z - mean) * rstd * gv.z + bv.z;
        y.w = (v[j].w - mean) * rstd * gv.w + bv.w;
        if (WF32) *(float4*)(Y + (long)r * DM + c) = y;
        if (WF16) {
            __half2 h0 = __floats2half2_rn(y.x, y.y);
            __half2 h1 = __floats2half2_rn(y.z, y.w);
            uint2 u = { *(unsigned*)&h0, *(unsigned*)&h1 };
            *(uint2*)(Yh + (long)r * DM + c) = u;
        }
    }
}

// ============================================================
extern "C" void kernel_launch(void* const* d_in, const int* in_sizes, int n_in,
                              void* d_out, int out_size)
{
    const float* x   = (const float*)d_in[0];
    const float* Wq  = (const float*)d_in[1];
    const float* bq  = (const float*)d_in[2];
    const float* Wk  = (const float*)d_in[3];
    const float* bk  = (const float*)d_in[4];
    const float* Wv  = (const float*)d_in[5];
    const float* bv  = (const float*)d_in[6];
    const float* Wo  = (const float*)d_in[7];
    const float* bo  = (const float*)d_in[8];
    const float* W1  = (const float*)d_in[9];
    const float* b1  = (const float*)d_in[10];
    const float* W2  = (const float*)d_in[11];
    const float* b2  = (const float*)d_in[12];
    const float* g1  = (const float*)d_in[13];
    const float* be1 = (const float*)d_in[14];
    const float* g2  = (const float*)d_in[15];
    const float* be2 = (const float*)d_in[16];
    float* out = (float*)d_out;

    float *y1, *y1b, *y2, *y2b, *bqkv, *po, *pmv, *plv;
    cudaGetSymbolAddress((void**)&y1,   g_y1);
    cudaGetSymbolAddress((void**)&y1b,  g_y1b);
    cudaGetSymbolAddress((void**)&y2,   g_y2);
    cudaGetSymbolAddress((void**)&y2b,  g_y2b);
    cudaGetSymbolAddress((void**)&bqkv, g_bqkv);
    cudaGetSymbolAddress((void**)&po,   g_po);
    cudaGetSymbolAddress((void**)&pmv,  g_pm);
    cudaGetSymbolAddress((void**)&plv,  g_pl);

    __half *x16, *ab, *h16, *f1;
    cudaGetSymbolAddress((void**)&x16, g_x16);
    cudaGetSymbolAddress((void**)&ab,  g_ab);
    cudaGetSymbolAddress((void**)&h16, g_h16);
    cudaGetSymbolAddress((void**)&f1,  g_f1);

    __half *wqkv, *wo, *w1, *w2;
    cudaGetSymbolAddress((void**)&wqkv, g_wqkv);
    cudaGetSymbolAddress((void**)&wo, g_wo);
    cudaGetSymbolAddress((void**)&w1, g_w1);
    cudaGetSymbolAddress((void**)&w2, g_w2);

    __half *qs, *ks, *vs;
    cudaGetSymbolAddress((void**)&qs, g_qs);
    cudaGetSymbolAddress((void**)&ks, g_ks);
    cudaGetSymbolAddress((void**)&vs, g_vs);

    cudaFuncSetAttribute(gemm_h1<2, false, false, false, false>,
                         cudaFuncAttributeMaxDynamicSharedMemorySize, GSMEM);
    cudaFuncSetAttribute(gemm_h1<0, false, true, false, true>,
                         cudaFuncAttributeMaxDynamicSharedMemorySize, GSMEM);
    cudaFuncSetAttribute(gemm_h1<0, false, true, true, true>,
                         cudaFuncAttributeMaxDynamicSharedMemorySize, GSMEM);
    cudaFuncSetAttribute(gemm_h1<1, true, false, false, false>,
                         cudaFuncAttributeMaxDynamicSharedMemorySize, GSMEM);
    cudaFuncSetAttribute(attn_tc, cudaFuncAttributeMaxDynamicSharedMemorySize, AT_SMEM);

    dim3 blk(256);

    prep_all<<<9993, blk>>>(Wq, Wk, Wv, Wo, W1, W2, wqkv, wo, w1, w2,
                            x, x16, bq, bk, bv, bqkv);

    gemm_h1<2, false, false, false, false><<<dim3(18, 32), blk, GSMEM>>>(
        x16, wqkv, bqkv, nullptr, nullptr, nullptr, nullptr, nullptr, DM, 3 * DM);

    attn_tc<<<dim3(48, NH), blk, AT_SMEM>>>(qs, ks, vs, ab, po, pmv, plv);
    attn_combine<<<NSPLIT_TILES * 8, blk>>>(po, pmv, plv, ab);

    gemm_h1<0, false, true, false, true><<<dim3(6, 32, 2), blk, GSMEM>>>(
        ab, wo, bo, x, nullptr, y1, y1b, nullptr, DM, DM);

    ln_kernel<false, true><<<TSEQ / 8, blk>>>(y1, y1b, g1, be1, nullptr, h16);

    gemm_h1<1, true, false, false, false><<<dim3(24, 32), blk, GSMEM>>>(
        h16, w1, b1, nullptr, nullptr, nullptr, nullptr, f1, DM, DFF);
    gemm_h1<0, false, true, true, true><<<dim3(6, 32, 2), blk, GSMEM>>>(
        f1, w2, b2, nullptr, h16, y2, y2b, nullptr, DFF, DM);

    ln_kernel<true, false><<<TSEQ / 8, blk>>>(y2, y2b, g2, be2, out, nullptr);
}